// round 2
// baseline (speedup 1.0000x reference)
#include <cuda_runtime.h>
#include <cuda_bf16.h>

#define N_EXPERTS 32
#define H 256
#define BATCH 16
#define SEQ 8192
#define ALPHA 0.001f

#define TOK_PER_BLOCK 256
#define TILE 16            // tokens per phase-A/B tile
#define PSTRIDE 9          // padded 8 -> 9 floats per (t,e) partial row

// Scratch for aux-loss statistics (device globals: no allocation allowed).
__device__ float g_sums[BATCH * N_EXPERTS];   // sum of softmax scores per (batch, expert)
__device__ float g_cnts[BATCH * N_EXPERTS];   // top-1 assignment counts per (batch, expert)

__global__ void zero_kernel() {
    int i = threadIdx.x;                      // 512 threads
    g_sums[i] = 0.0f;
    g_cnts[i] = 0.0f;
}

// ---- packed f32x2 helpers (Blackwell) ----
__device__ __forceinline__ unsigned long long f2_mul(unsigned long long a, unsigned long long b) {
    unsigned long long d;
    asm("mul.rn.f32x2 %0, %1, %2;" : "=l"(d) : "l"(a), "l"(b));
    return d;
}
__device__ __forceinline__ unsigned long long f2_fma(unsigned long long a, unsigned long long b,
                                                     unsigned long long c) {
    unsigned long long d;
    asm("fma.rn.f32x2 %0, %1, %2, %3;" : "=l"(d) : "l"(a), "l"(b), "l"(c));
    return d;
}
__device__ __forceinline__ float f2_hadd(unsigned long long a) {
    unsigned lo, hi;
    asm("mov.b64 {%0, %1}, %2;" : "=r"(lo), "=r"(hi) : "l"(a));
    return __uint_as_float(lo) + __uint_as_float(hi);
}
// 16-byte global load into two packed u64 (read-only path)
__device__ __forceinline__ void ldg_v2u64(const float* p, unsigned long long& a,
                                          unsigned long long& b) {
    asm("ld.global.nc.v2.b64 {%0, %1}, [%2];" : "=l"(a), "=l"(b) : "l"(p));
}

// W-stationary gating kernel.
// Block = 8 warps. Warp wi owns k-slice [32*wi, 32*wi+32); lane = expert index;
// each lane holds w[lane][slice] in registers for the whole block lifetime.
// Tokens processed in tiles of 16: phase A computes per-slice partial logits into
// smem (pre-transposed layout), phase B reduces 8 partials -> full logits with
// lane==expert, then softmax/argmax with only 11 shuffles per token.
__global__ __launch_bounds__(256, 3)
void gate_kernel(const float* __restrict__ x, const float* __restrict__ w,
                 float* __restrict__ out_idx, float* __restrict__ out_w) {
    __shared__ float part[TILE * N_EXPERTS * PSTRIDE];   // 18.4 KB
    __shared__ float s_sum[N_EXPERTS];
    __shared__ float s_cnt[N_EXPERTS];

    const int tid = threadIdx.x;
    const int lane = tid & 31;
    const int wi = tid >> 5;

    if (tid < N_EXPERTS) { s_sum[tid] = 0.0f; s_cnt[tid] = 0.0f; }

    // Load this lane's weight slice into registers: w[lane][32*wi .. 32*wi+32)
    unsigned long long wreg[16];
    {
        const float* wp = w + lane * H + wi * 32;
        #pragma unroll
        for (int j = 0; j < 8; j++)
            ldg_v2u64(wp + 4 * j, wreg[2 * j], wreg[2 * j + 1]);
    }
    __syncthreads();

    const int tok_base = blockIdx.x * TOK_PER_BLOCK;
    const float* xslice = x + (size_t)tok_base * H + wi * 32;   // phase-A base for this warp

    float score_acc = 0.0f;   // lane == expert: sum of softmax scores (this block's tokens)
    float cnt_acc = 0.0f;     // lane == expert: top-1 assignment count

    for (int tile = 0; tile < TOK_PER_BLOCK / TILE; tile++) {
        // ---------- Phase A: partial dot products ----------
        const float* xt = xslice + (size_t)tile * TILE * H;
        #pragma unroll 1
        for (int t = 0; t < TILE; t++) {
            const float* xp = xt + (size_t)t * H;
            unsigned long long xr[8];
            // first 16 floats of the slice
            ldg_v2u64(xp + 0,  xr[0], xr[1]);
            ldg_v2u64(xp + 4,  xr[2], xr[3]);
            ldg_v2u64(xp + 8,  xr[4], xr[5]);
            ldg_v2u64(xp + 12, xr[6], xr[7]);
            unsigned long long accA = f2_mul(xr[0], wreg[0]);
            unsigned long long accB = f2_mul(xr[1], wreg[1]);
            accA = f2_fma(xr[2], wreg[2], accA);
            accB = f2_fma(xr[3], wreg[3], accB);
            accA = f2_fma(xr[4], wreg[4], accA);
            accB = f2_fma(xr[5], wreg[5], accB);
            accA = f2_fma(xr[6], wreg[6], accA);
            accB = f2_fma(xr[7], wreg[7], accB);
            // second 16 floats
            ldg_v2u64(xp + 16, xr[0], xr[1]);
            ldg_v2u64(xp + 20, xr[2], xr[3]);
            ldg_v2u64(xp + 24, xr[4], xr[5]);
            ldg_v2u64(xp + 28, xr[6], xr[7]);
            accA = f2_fma(xr[0], wreg[8],  accA);
            accB = f2_fma(xr[1], wreg[9],  accB);
            accA = f2_fma(xr[2], wreg[10], accA);
            accB = f2_fma(xr[3], wreg[11], accB);
            accA = f2_fma(xr[4], wreg[12], accA);
            accB = f2_fma(xr[5], wreg[13], accB);
            accA = f2_fma(xr[6], wreg[14], accA);
            accB = f2_fma(xr[7], wreg[15], accB);

            const float p = f2_hadd(accA) + f2_hadd(accB);
            // pre-transposed partial store: conflict-free (stride 9 floats, 9 odd)
            part[(t * N_EXPERTS + lane) * PSTRIDE + wi] = p;
        }
        __syncthreads();

        // ---------- Phase B: reduce partials + softmax/argmax ----------
        // Warp wi handles tokens {2*wi, 2*wi+1} of this tile.
        #pragma unroll
        for (int tt = 0; tt < 2; tt++) {
            const int t = wi * 2 + tt;
            const float* pr = &part[(t * N_EXPERTS + lane) * PSTRIDE];
            float v = ((pr[0] + pr[1]) + (pr[2] + pr[3])) +
                      ((pr[4] + pr[5]) + (pr[6] + pr[7]));   // logit for expert == lane

            float m = v;
            #pragma unroll
            for (int off = 16; off; off >>= 1)
                m = fmaxf(m, __shfl_xor_sync(0xffffffffu, m, off));
            const unsigned bal = __ballot_sync(0xffffffffu, v == m);
            const int mi = __ffs(bal) - 1;                   // lowest index on ties

            const float e = __expf(v - m);
            float s = e;
            #pragma unroll
            for (int off = 16; off; off >>= 1)
                s += __shfl_xor_sync(0xffffffffu, s, off);
            const float inv = __fdividef(1.0f, s);

            score_acc += e * inv;                            // per-expert score (lane==expert)
            if (lane == mi) cnt_acc += 1.0f;
            if (lane == 0) {
                const int gt = tok_base + tile * TILE + t;
                out_idx[gt] = (float)mi;
                out_w[gt] = inv;                             // exp(0)/s for the argmax expert
            }
        }
        __syncthreads();   // protect `part` before next tile's phase A
    }

    // Block-level aux accumulation -> global (8 smem atomics per expert).
    atomicAdd(&s_sum[lane], score_acc);
    atomicAdd(&s_cnt[lane], cnt_acc);
    __syncthreads();
    if (tid < N_EXPERTS) {
        const int batch = blockIdx.x >> 5;   // 32 blocks (8192 tokens) per batch
        atomicAdd(&g_sums[batch * N_EXPERTS + tid], s_sum[tid]);
        atomicAdd(&g_cnts[batch * N_EXPERTS + tid], s_cnt[tid]);
    }
}

__global__ void aux_kernel(float* __restrict__ out_aux) {
    const int i = threadIdx.x;   // 512 threads = BATCH*N_EXPERTS
    float v = (g_cnts[i] * ((float)N_EXPERTS / (float)SEQ)) *
              (g_sums[i] * (1.0f / (float)SEQ));
    #pragma unroll
    for (int off = 16; off; off >>= 1) v += __shfl_xor_sync(0xffffffffu, v, off);
    __shared__ float red[16];
    if ((i & 31) == 0) red[i >> 5] = v;
    __syncthreads();
    if (i < 32) {
        float t = (i < 16) ? red[i] : 0.0f;
        #pragma unroll
        for (int off = 16; off; off >>= 1) t += __shfl_xor_sync(0xffffffffu, t, off);
        if (i == 0) out_aux[0] = t * (ALPHA / (float)BATCH);
    }
}

extern "C" void kernel_launch(void* const* d_in, const int* in_sizes, int n_in,
                              void* d_out, int out_size) {
    const float* x = (const float*)d_in[0];   // [16, 8192, 256] f32
    const float* w = (const float*)d_in[1];   // [32, 256] f32
    float* out = (float*)d_out;               // [N idx | N weight | 1 aux], f32

    const int n_tokens = in_sizes[0] / H;     // 131072
    const int n_blocks = n_tokens / TOK_PER_BLOCK;   // 512

    zero_kernel<<<1, BATCH * N_EXPERTS>>>();
    gate_kernel<<<n_blocks, 256>>>(x, w, out, out + n_tokens);
    aux_kernel<<<1, BATCH * N_EXPERTS>>>(out + 2 * n_tokens);
}

// round 3
// speedup vs baseline: 2.8698x; 2.8698x over previous
#include <cuda_runtime.h>
#include <cuda_bf16.h>

#define N_EXPERTS 32
#define H 256
#define BATCH 16
#define SEQ 8192
#define ALPHA 0.001f

#define TOK_PER_BLOCK 256
#define TILE 16            // tokens per pipeline stage / phase tile
#define NTILES (TOK_PER_BLOCK / TILE)   // 16
#define STAGES 3
#define PSTRIDE 9          // padded partial row stride (floats)
#define NBLOCKS 512

// Per-block aux partials (written every launch -> no zeroing kernel needed).
__device__ float g_bsum[NBLOCKS * N_EXPERTS];
__device__ float g_bcnt[NBLOCKS * N_EXPERTS];
__device__ unsigned g_ctr = 0;          // last-block-done counter (self-resetting)

// ---- packed f32x2 helpers (Blackwell) ----
__device__ __forceinline__ unsigned long long f2_mul(unsigned long long a, unsigned long long b) {
    unsigned long long d;
    asm("mul.rn.f32x2 %0, %1, %2;" : "=l"(d) : "l"(a), "l"(b));
    return d;
}
__device__ __forceinline__ unsigned long long f2_fma(unsigned long long a, unsigned long long b,
                                                     unsigned long long c) {
    unsigned long long d;
    asm("fma.rn.f32x2 %0, %1, %2, %3;" : "=l"(d) : "l"(a), "l"(b), "l"(c));
    return d;
}
__device__ __forceinline__ float f2_hadd(unsigned long long a) {
    unsigned lo, hi;
    asm("mov.b64 {%0, %1}, %2;" : "=r"(lo), "=r"(hi) : "l"(a));
    return __uint_as_float(lo) + __uint_as_float(hi);
}
__device__ __forceinline__ void ldg_v2u64(const float* p, unsigned long long& a,
                                          unsigned long long& b) {
    asm("ld.global.nc.v2.b64 {%0, %1}, [%2];" : "=l"(a), "=l"(b) : "l"(p));
}

// ---- cp.async helpers ----
__device__ __forceinline__ void cp_async16(void* smem_dst, const void* gsrc) {
    unsigned saddr = (unsigned)__cvta_generic_to_shared(smem_dst);
    asm volatile("cp.async.cg.shared.global [%0], [%1], 16;" :: "r"(saddr), "l"(gsrc));
}
#define CP_COMMIT()  asm volatile("cp.async.commit_group;")
#define CP_WAIT(N)   asm volatile("cp.async.wait_group %0;" :: "n"(N))

// Fused MoE gate kernel: W-stationary (warp wi owns k-slice [32wi,32wi+32),
// lane = expert, weights in registers). x streamed global->smem via 3-stage
// cp.async pipeline; per-slice partial logits meet in smem pre-transposed so
// phase B has lane==expert with zero transpose shuffles.
extern __shared__ float smem[];   // [STAGES*TILE*H xbuf | 2*TILE*32*PSTRIDE part]

__global__ __launch_bounds__(256)
void gate_kernel(const float* __restrict__ x, const float* __restrict__ w,
                 float* __restrict__ out_idx, float* __restrict__ out_w,
                 float* __restrict__ out_aux) {
    float* xbuf = smem;                                  // STAGES * 4096 floats
    float* part = smem + STAGES * TILE * H;              // 2 * 4608 floats

    const int tid = threadIdx.x;
    const int lane = tid & 31;
    const int wi = tid >> 5;
    const int bid = blockIdx.x;
    const int tok_base = bid * TOK_PER_BLOCK;

    // Weight slice into registers: lane = expert, cols [32wi, 32wi+32).
    unsigned long long wreg[16];
    {
        const float* wp = w + lane * H + wi * 32;
        #pragma unroll
        for (int j = 0; j < 8; j++)
            ldg_v2u64(wp + 4 * j, wreg[2 * j], wreg[2 * j + 1]);
    }

    // Pipeline prologue: prefetch tiles 0..STAGES-2.
    const float* xg = x + (size_t)tok_base * H;
    #pragma unroll
    for (int s = 0; s < STAGES - 1; s++) {
        float* dst = xbuf + s * (TILE * H);
        const float* src = xg + s * (TILE * H);
        #pragma unroll
        for (int j = 0; j < 4; j++) {
            int c = tid + j * 256;                       // 1024 16B chunks per tile
            cp_async16(dst + c * 4, src + c * 4);
        }
        CP_COMMIT();
    }

    float score_acc = 0.0f;   // lane == expert
    float cnt_acc = 0.0f;

    for (int t = 0; t < NTILES; t++) {
        CP_WAIT(STAGES - 2);
        __syncthreads();

        // ---------- Phase A: partial logits from smem ----------
        const float* xb = xbuf + (t % STAGES) * (TILE * H) + wi * 32;
        float* pb = part + (t & 1) * (TILE * N_EXPERTS * PSTRIDE);
        #pragma unroll 4
        for (int tok = 0; tok < TILE; tok++) {
            const ulonglong2* xp = (const ulonglong2*)(xb + tok * H);
            ulonglong2 v0 = xp[0], v1 = xp[1], v2 = xp[2], v3 = xp[3];
            ulonglong2 v4 = xp[4], v5 = xp[5], v6 = xp[6], v7 = xp[7];
            unsigned long long aA = f2_mul(v0.x, wreg[0]);
            unsigned long long aB = f2_mul(v0.y, wreg[1]);
            unsigned long long aC = f2_mul(v1.x, wreg[2]);
            unsigned long long aD = f2_mul(v1.y, wreg[3]);
            aA = f2_fma(v2.x, wreg[4],  aA);
            aB = f2_fma(v2.y, wreg[5],  aB);
            aC = f2_fma(v3.x, wreg[6],  aC);
            aD = f2_fma(v3.y, wreg[7],  aD);
            aA = f2_fma(v4.x, wreg[8],  aA);
            aB = f2_fma(v4.y, wreg[9],  aB);
            aC = f2_fma(v5.x, wreg[10], aC);
            aD = f2_fma(v5.y, wreg[11], aD);
            aA = f2_fma(v6.x, wreg[12], aA);
            aB = f2_fma(v6.y, wreg[13], aB);
            aC = f2_fma(v7.x, wreg[14], aC);
            aD = f2_fma(v7.y, wreg[15], aD);
            const float p = (f2_hadd(aA) + f2_hadd(aB)) + (f2_hadd(aC) + f2_hadd(aD));
            pb[(tok * N_EXPERTS + lane) * PSTRIDE + wi] = p;   // conflict-free (9 odd)
        }
        __syncthreads();

        // Prefetch tile t+STAGES-1 (its buffer slot was consumed in tile t-1).
        if (t + STAGES - 1 < NTILES) {
            float* dst = xbuf + ((t + STAGES - 1) % STAGES) * (TILE * H);
            const float* src = xg + (t + STAGES - 1) * (TILE * H);
            #pragma unroll
            for (int j = 0; j < 4; j++) {
                int c = tid + j * 256;
                cp_async16(dst + c * 4, src + c * 4);
            }
        }
        CP_COMMIT();

        // ---------- Phase B: warp wi -> tokens {2wi, 2wi+1} of this tile ----------
        #pragma unroll
        for (int tt = 0; tt < 2; tt++) {
            const int tok = wi * 2 + tt;
            const float* pr = pb + (tok * N_EXPERTS + lane) * PSTRIDE;
            float v = ((pr[0] + pr[1]) + (pr[2] + pr[3])) +
                      ((pr[4] + pr[5]) + (pr[6] + pr[7]));   // logit, expert == lane

            float m = v;
            #pragma unroll
            for (int off = 16; off; off >>= 1)
                m = fmaxf(m, __shfl_xor_sync(0xffffffffu, m, off));
            const unsigned bal = __ballot_sync(0xffffffffu, v == m);
            const int mi = __ffs(bal) - 1;                   // lowest index on ties

            const float e = __expf(v - m);
            float s = e;
            #pragma unroll
            for (int off = 16; off; off >>= 1)
                s += __shfl_xor_sync(0xffffffffu, s, off);
            const float inv = __fdividef(1.0f, s);

            score_acc += e * inv;
            if (lane == mi) cnt_acc += 1.0f;
            if (lane == 0) {
                const int gt = tok_base + t * TILE + tok;
                out_idx[gt] = (float)mi;
                out_w[gt] = inv;
            }
        }
    }

    // ---------- Per-block aux partials ----------
    __syncthreads();                       // part no longer needed by phase A/B
    part[wi * 32 + lane] = score_acc;
    part[256 + wi * 32 + lane] = cnt_acc;
    __syncthreads();
    if (wi == 0) {
        float s = 0.0f;
        #pragma unroll
        for (int j = 0; j < 8; j++) s += part[j * 32 + lane];
        g_bsum[bid * N_EXPERTS + lane] = s;
        __threadfence();
    }
    if (wi == 1) {
        float c = 0.0f;
        #pragma unroll
        for (int j = 0; j < 8; j++) c += part[256 + j * 32 + lane];
        g_bcnt[bid * N_EXPERTS + lane] = c;
        __threadfence();
    }
    __syncthreads();

    // ---------- Last block computes aux loss ----------
    __shared__ unsigned s_old;
    if (tid == 0) s_old = atomicAdd(&g_ctr, 1u);
    __syncthreads();
    if (s_old == (unsigned)(gridDim.x - 1)) {
        __threadfence();
        float acc = 0.0f;
        for (int p = tid; p < BATCH * N_EXPERTS; p += 256) {
            const int b = p >> 5, e = p & 31;
            float sc = 0.0f, cn = 0.0f;
            #pragma unroll
            for (int j = 0; j < 32; j++) {               // 32 blocks per batch
                sc += g_bsum[(b * 32 + j) * N_EXPERTS + e];
                cn += g_bcnt[(b * 32 + j) * N_EXPERTS + e];
            }
            acc += (cn * ((float)N_EXPERTS / (float)SEQ)) * (sc * (1.0f / (float)SEQ));
        }
        #pragma unroll
        for (int off = 16; off; off >>= 1)
            acc += __shfl_xor_sync(0xffffffffu, acc, off);
        __shared__ float red[8];
        if (lane == 0) red[wi] = acc;
        __syncthreads();
        if (tid == 0) {
            float tot = 0.0f;
            #pragma unroll
            for (int j = 0; j < 8; j++) tot += red[j];
            out_aux[0] = tot * (ALPHA / (float)BATCH);
            g_ctr = 0;                                   // reset for next replay
        }
    }
}

extern "C" void kernel_launch(void* const* d_in, const int* in_sizes, int n_in,
                              void* d_out, int out_size) {
    const float* x = (const float*)d_in[0];   // [16, 8192, 256] f32
    const float* w = (const float*)d_in[1];   // [32, 256] f32
    float* out = (float*)d_out;               // [N idx | N weight | 1 aux], f32

    const int n_tokens = in_sizes[0] / H;     // 131072
    const int n_blocks = n_tokens / TOK_PER_BLOCK;   // 512

    const int smem_bytes = (STAGES * TILE * H + 2 * TILE * N_EXPERTS * PSTRIDE) * 4; // 86016
    static bool configured = false;
    if (!configured) {
        cudaFuncSetAttribute(gate_kernel, cudaFuncAttributeMaxDynamicSharedMemorySize,
                             smem_bytes);
        configured = true;
    }
    gate_kernel<<<n_blocks, 256, smem_bytes>>>(x, w, out, out + n_tokens,
                                               out + 2 * n_tokens);
}

// round 7
// speedup vs baseline: 3.7016x; 1.2898x over previous
#include <cuda_runtime.h>
#include <cuda_bf16.h>

#define N_EXPERTS 32
#define H 256
#define BATCH 16
#define SEQ 8192
#define ALPHA 0.001f

#define TPB_TOKENS 128          // tokens per block
#define TILE 8                  // tokens per pipeline tile
#define NTILES (TPB_TOKENS / TILE)   // 16
#define STAGES 3
#define XROW 288                // words per token row in xbuf (256 data + skew pads)
#define XTILE (TILE * XROW)     // 2304 words per stage
#define PSTR 5                  // partials per logit (4) + 1 pad
#define PARTW (TILE * N_EXPERTS * PSTR)   // 1280 words per part buffer
#define NBLOCKS 1024
#define BLK_PER_BATCH 64

// Per-block aux partials (written every launch -> no zeroing pass needed).
__device__ float g_bsum[NBLOCKS * N_EXPERTS];
__device__ float g_bcnt[NBLOCKS * N_EXPERTS];
__device__ unsigned g_ctr = 0;          // last-block-done counter (self-resetting)

// ---- packed f32x2 helpers (Blackwell) ----
__device__ __forceinline__ unsigned long long f2_mul(unsigned long long a, unsigned long long b) {
    unsigned long long d;
    asm("mul.rn.f32x2 %0, %1, %2;" : "=l"(d) : "l"(a), "l"(b));
    return d;
}
__device__ __forceinline__ unsigned long long f2_fma(unsigned long long a, unsigned long long b,
                                                     unsigned long long c) {
    unsigned long long d;
    asm("fma.rn.f32x2 %0, %1, %2, %3;" : "=l"(d) : "l"(a), "l"(b), "l"(c));
    return d;
}
__device__ __forceinline__ float f2_hadd(unsigned long long a) {
    unsigned lo, hi;
    asm("mov.b64 {%0, %1}, %2;" : "=r"(lo), "=r"(hi) : "l"(a));
    return __uint_as_float(lo) + __uint_as_float(hi);
}
__device__ __forceinline__ void ldg_v2u64(const float* p, unsigned long long& a,
                                          unsigned long long& b) {
    asm("ld.global.nc.v2.b64 {%0, %1}, [%2];" : "=l"(a), "=l"(b) : "l"(p));
}

// ---- cp.async helpers ----
__device__ __forceinline__ void cp_async16(void* smem_dst, const void* gsrc) {
    unsigned saddr = (unsigned)__cvta_generic_to_shared(smem_dst);
    asm volatile("cp.async.cg.shared.global [%0], [%1], 16;" :: "r"(saddr), "l"(gsrc));
}
#define CP_COMMIT()  asm volatile("cp.async.commit_group;")
#define CP_WAIT(N)   asm volatile("cp.async.wait_group %0;" :: "n"(N))

// MoE gate: 4 warps, W-stationary, 2 experts/lane.
// Lane L of warp WI holds experts {L&15, (L&15)+16} over k-slice 32*(2*WI+(L>>4)).
// x tile staged via cp.async with +16B skew per 128B so each LDS.128 serves the
// two 16-lane groups from disjoint banks (dual broadcast, conflict-free).
__global__ __launch_bounds__(128, 5)
void gate_kernel(const float* __restrict__ x, const float* __restrict__ w,
                 float* __restrict__ out_idx, float* __restrict__ out_w,
                 float* __restrict__ out_aux) {
    __shared__ float xbuf[STAGES * XTILE];   // 27.6 KB
    __shared__ float part[2 * PARTW];        // 10.2 KB (double-buffered)
    __shared__ float red4[4];
    __shared__ unsigned s_old;

    const int tid = threadIdx.x;
    const int lane = tid & 31;
    const int wi = tid >> 5;                 // 0..3
    const int grp = lane >> 4;               // 0/1: which k-slice of the pair
    const int bid = blockIdx.x;
    const int tok_base = bid * TPB_TOKENS;

    // Weight regs: expert e0 = lane&15 and e1 = e0+16, k-cols [ks*32, ks*32+32).
    const int ks = 2 * wi + grp;
    unsigned long long w0[16], w1[16];
    {
        const float* wp0 = w + (lane & 15) * H + ks * 32;
        const float* wp1 = wp0 + 16 * H;
        #pragma unroll
        for (int j = 0; j < 8; j++) {
            ldg_v2u64(wp0 + 4 * j, w0[2 * j], w0[2 * j + 1]);
            ldg_v2u64(wp1 + 4 * j, w1[2 * j], w1[2 * j + 1]);
        }
    }

    // cp.async chunk mapping for this thread: 4 chunks/tile.
    // chunk c (0..63) of row r lands at word r*XROW + c*4 + (c>>3)*4.
    const int pf_row = tid >> 4;             // 0..7
    const int pf_c0 = tid & 15;              // +16k, k=0..3
    const float* xg = x + (size_t)tok_base * H;

    // Prologue: prefetch tiles 0,1.
    #pragma unroll
    for (int s = 0; s < STAGES - 1; s++) {
        float* dst = xbuf + s * XTILE + pf_row * XROW;
        const float* src = xg + s * (TILE * H) + pf_row * H;
        #pragma unroll
        for (int k = 0; k < 4; k++) {
            int c = pf_c0 + 16 * k;
            cp_async16(dst + c * 4 + (c >> 3) * 4, src + c * 4);
        }
        CP_COMMIT();
    }

    float score_acc = 0.0f;   // lane == expert (phase B view)
    float cnt_acc = 0.0f;

    for (int t = 0; t < NTILES; t++) {
        CP_WAIT(1);
        __syncthreads();

        // ---------- Phase A ----------
        const float* xb = xbuf + (t % STAGES) * XTILE + ks * 36;  // 36 words = 8 chunks + skew
        float* pb = part + (t & 1) * PARTW;
        #pragma unroll 4
        for (int tok = 0; tok < TILE; tok++) {
            const ulonglong2* xp = (const ulonglong2*)(xb + tok * XROW);
            unsigned long long a0, a1, b0, b1;
            {
                ulonglong2 v0 = xp[0], v1 = xp[1], v2 = xp[2], v3 = xp[3];
                a0 = f2_mul(v0.x, w0[0]);  a1 = f2_mul(v0.y, w0[1]);
                b0 = f2_mul(v0.x, w1[0]);  b1 = f2_mul(v0.y, w1[1]);
                a0 = f2_fma(v1.x, w0[2], a0);  a1 = f2_fma(v1.y, w0[3], a1);
                b0 = f2_fma(v1.x, w1[2], b0);  b1 = f2_fma(v1.y, w1[3], b1);
                a0 = f2_fma(v2.x, w0[4], a0);  a1 = f2_fma(v2.y, w0[5], a1);
                b0 = f2_fma(v2.x, w1[4], b0);  b1 = f2_fma(v2.y, w1[5], b1);
                a0 = f2_fma(v3.x, w0[6], a0);  a1 = f2_fma(v3.y, w0[7], a1);
                b0 = f2_fma(v3.x, w1[6], b0);  b1 = f2_fma(v3.y, w1[7], b1);
            }
            {
                ulonglong2 v4 = xp[4], v5 = xp[5], v6 = xp[6], v7 = xp[7];
                a0 = f2_fma(v4.x, w0[8],  a0);  a1 = f2_fma(v4.y, w0[9],  a1);
                b0 = f2_fma(v4.x, w1[8],  b0);  b1 = f2_fma(v4.y, w1[9],  b1);
                a0 = f2_fma(v5.x, w0[10], a0);  a1 = f2_fma(v5.y, w0[11], a1);
                b0 = f2_fma(v5.x, w1[10], b0);  b1 = f2_fma(v5.y, w1[11], b1);
                a0 = f2_fma(v6.x, w0[12], a0);  a1 = f2_fma(v6.y, w0[13], a1);
                b0 = f2_fma(v6.x, w1[12], b0);  b1 = f2_fma(v6.y, w1[13], b1);
                a0 = f2_fma(v7.x, w0[14], a0);  a1 = f2_fma(v7.y, w0[15], a1);
                b0 = f2_fma(v7.x, w1[14], b0);  b1 = f2_fma(v7.y, w1[15], b1);
            }
            float p0 = f2_hadd(a0) + f2_hadd(a1);          // expert lane&15
            float p1 = f2_hadd(b0) + f2_hadd(b1);          // expert (lane&15)+16
            // combine the two k-slices of the pair (lanes L and L^16 swap)
            p0 += __shfl_xor_sync(0xffffffffu, p0, 16);
            p1 += __shfl_xor_sync(0xffffffffu, p1, 16);
            const float val = (grp == 0) ? p0 : p1;        // store expert == lane
            pb[(tok * N_EXPERTS + lane) * PSTR + wi] = val; // stride-5: conflict-free
        }
        __syncthreads();

        // Prefetch tile t+2.
        if (t + STAGES - 1 < NTILES) {
            float* dst = xbuf + ((t + STAGES - 1) % STAGES) * XTILE + pf_row * XROW;
            const float* src = xg + (t + STAGES - 1) * (TILE * H) + pf_row * H;
            #pragma unroll
            for (int k = 0; k < 4; k++) {
                int c = pf_c0 + 16 * k;
                cp_async16(dst + c * 4 + (c >> 3) * 4, src + c * 4);
            }
        }
        CP_COMMIT();

        // ---------- Phase B: warp wi -> tokens {2wi, 2wi+1} ----------
        #pragma unroll
        for (int tt = 0; tt < 2; tt++) {
            const int tok = wi * 2 + tt;
            const float* pr = pb + (tok * N_EXPERTS + lane) * PSTR;
            float v = (pr[0] + pr[1]) + (pr[2] + pr[3]);   // logit, expert == lane

            float m = v;
            #pragma unroll
            for (int off = 16; off; off >>= 1)
                m = fmaxf(m, __shfl_xor_sync(0xffffffffu, m, off));
            const unsigned bal = __ballot_sync(0xffffffffu, v == m);
            const int mi = __ffs(bal) - 1;                 // lowest index on ties

            const float e = __expf(v - m);
            float s = e;
            #pragma unroll
            for (int off = 16; off; off >>= 1)
                s += __shfl_xor_sync(0xffffffffu, s, off);
            const float inv = __fdividef(1.0f, s);

            score_acc += e * inv;
            if (lane == mi) cnt_acc += 1.0f;
            if (lane == 0) {
                const int gt = tok_base + t * TILE + tok;
                out_idx[gt] = (float)mi;
                out_w[gt] = inv;
            }
        }
    }

    // ---------- Per-block aux partials ----------
    __syncthreads();
    part[wi * 32 + lane] = score_acc;
    part[128 + wi * 32 + lane] = cnt_acc;
    __syncthreads();
    if (wi == 0) {
        float s = (part[lane] + part[32 + lane]) + (part[64 + lane] + part[96 + lane]);
        g_bsum[bid * N_EXPERTS + lane] = s;
        __threadfence();
    }
    if (wi == 1) {
        float c = (part[128 + lane] + part[160 + lane]) + (part[192 + lane] + part[224 + lane]);
        g_bcnt[bid * N_EXPERTS + lane] = c;
        __threadfence();
    }
    __syncthreads();

    // ---------- Last block computes aux loss ----------
    if (tid == 0) s_old = atomicAdd(&g_ctr, 1u);
    __syncthreads();
    if (s_old == (unsigned)(gridDim.x - 1)) {
        __threadfence();
        float acc = 0.0f;
        for (int p = tid; p < BATCH * N_EXPERTS; p += 128) {
            const int b = p >> 5, e = p & 31;
            float sc = 0.0f, cn = 0.0f;
            #pragma unroll 8
            for (int j = 0; j < BLK_PER_BATCH; j++) {
                sc += g_bsum[(b * BLK_PER_BATCH + j) * N_EXPERTS + e];
                cn += g_bcnt[(b * BLK_PER_BATCH + j) * N_EXPERTS + e];
            }
            acc += (cn * ((float)N_EXPERTS / (float)SEQ)) * (sc * (1.0f / (float)SEQ));
        }
        #pragma unroll
        for (int off = 16; off; off >>= 1)
            acc += __shfl_xor_sync(0xffffffffu, acc, off);
        if (lane == 0) red4[wi] = acc;
        __syncthreads();
        if (tid == 0) {
            out_aux[0] = ((red4[0] + red4[1]) + (red4[2] + red4[3])) * (ALPHA / (float)BATCH);
            g_ctr = 0;                                   // reset for next replay
        }
    }
}

extern "C" void kernel_launch(void* const* d_in, const int* in_sizes, int n_in,
                              void* d_out, int out_size) {
    const float* x = (const float*)d_in[0];   // [16, 8192, 256] f32
    const float* w = (const float*)d_in[1];   // [32, 256] f32
    float* out = (float*)d_out;               // [N idx | N weight | 1 aux], f32

    const int n_tokens = in_sizes[0] / H;     // 131072
    const int n_blocks = n_tokens / TPB_TOKENS;   // 1024

    gate_kernel<<<n_blocks, 128>>>(x, w, out, out + n_tokens, out + 2 * n_tokens);
}